// round 9
// baseline (speedup 1.0000x reference)
#include <cuda_runtime.h>
#include <cuda_bf16.h>

#define BATCH 64
#define SEQ   256
#define INP   1024
#define HID   1024
#define NG    4096
#define MTOT  (BATCH*SEQ)
#define NCTA  128

// -------- device scratch ----------
__device__ float g_gin[(size_t)MTOT * NG];   // 256 MB, T-MAJOR: row m = t*64 + b
__device__ float g_xt[(size_t)MTOT * INP];   // 64 MB: X permuted to t-major rows
__device__ float g_hbuf[2][BATCH * HID];
__device__ float g_c[BATCH * HID];
__device__ unsigned g_bar_count = 0;
__device__ unsigned g_bar_gen   = 0;
__device__ unsigned g_mt_cnt[128];           // per-m-tile completion counters

// -------- packed f32x2 helpers ----------
__device__ __forceinline__ unsigned long long pack2(float x) {
    unsigned long long r;
    unsigned xi = __float_as_uint(x);
    asm("mov.b64 %0, {%1, %1};" : "=l"(r) : "r"(xi));
    return r;
}
__device__ __forceinline__ void fma2(unsigned long long& d,
                                     unsigned long long a,
                                     unsigned long long b) {
    asm("fma.rn.f32x2 %0, %1, %2, %0;" : "+l"(d) : "l"(a), "l"(b));
}
__device__ __forceinline__ void add2(unsigned long long& d, unsigned long long s) {
    asm("add.rn.f32x2 %0, %0, %1;" : "+l"(d) : "l"(s));
}
__device__ __forceinline__ float2 unpack2(unsigned long long v) {
    unsigned lo, hi;
    asm("mov.b64 {%0, %1}, %2;" : "=r"(lo), "=r"(hi) : "l"(v));
    float2 f;
    f.x = __uint_as_float(lo);
    f.y = __uint_as_float(hi);
    return f;
}

// ---------------------------------------------------------------------------
// Kernel A: reset counters (runs before the fork each replay)
// ---------------------------------------------------------------------------
__global__ void reset_cnt() {
    if (threadIdx.x < 128) g_mt_cnt[threadIdx.x] = 0u;
}

// ---------------------------------------------------------------------------
// Kernel B: permute X rows to t-major (row m = t*64+b <- X row b*256+t)
// ---------------------------------------------------------------------------
__global__ __launch_bounds__(256) void transpose_x(const float* __restrict__ X) {
    size_t idx = (size_t)blockIdx.x * 256 + threadIdx.x;   // 0..4M-1 (float4 units)
    int m  = (int)(idx >> 8);        // 256 float4 per row
    int k4 = (int)(idx & 255);
    int t  = m >> 6;
    int b  = m & 63;
    float4 v = *(const float4*)(X + ((size_t)b * SEQ + t) * INP + k4 * 4);
    *(float4*)(g_xt + (size_t)m * INP + k4 * 4) = v;
}

// ---------------------------------------------------------------------------
// Kernel 1: Gin = Xt @ Wi^T + (b_i + b_h)  [proven core; reads g_xt,
// writes t-major gin, bumps per-m-tile counter at the end; 128-reg cap]
// ---------------------------------------------------------------------------
#define GKT 8
__global__ __launch_bounds__(256, 2) void gemm_input(const float* __restrict__ Wi,
                                                     const float* __restrict__ bi,
                                                     const float* __restrict__ bh) {
    __shared__ float As[2][GKT][132];
    __shared__ float Bs[2][GKT][132];

    const int tid   = threadIdx.x;
    const int mbase = blockIdx.y * 128;
    const int nbase = blockIdx.x * 128;
    const int ty    = tid >> 4;
    const int tx    = tid & 15;
    const int r0    = ty * 8;
    const int lrow  = tid >> 1;
    const int lkq   = (tid & 1) * 4;

    const float* Xrow  = g_xt + (size_t)(mbase + lrow) * INP + lkq;
    const float* Wirow = Wi   + (size_t)(nbase + lrow) * INP + lkq;

    unsigned long long acc[4][8];
#pragma unroll
    for (int i = 0; i < 4; i++)
#pragma unroll
        for (int j = 0; j < 8; j++) acc[i][j] = 0ull;

    {
        float4 va = *(const float4*)(Xrow);
        float4 vb = *(const float4*)(Wirow);
        As[0][lkq + 0][lrow] = va.x; As[0][lkq + 1][lrow] = va.y;
        As[0][lkq + 2][lrow] = va.z; As[0][lkq + 3][lrow] = va.w;
        Bs[0][lkq + 0][lrow] = vb.x; Bs[0][lkq + 1][lrow] = vb.y;
        Bs[0][lkq + 2][lrow] = vb.z; Bs[0][lkq + 3][lrow] = vb.w;
    }
    __syncthreads();

    const int NCHUNK = INP / GKT;
    for (int ck = 0; ck < NCHUNK; ck++) {
        const int cur = ck & 1;
        const int nxt = cur ^ 1;
        const bool pre = (ck + 1) < NCHUNK;
        float4 va, vb;
        if (pre) {
            int kn = (ck + 1) * GKT;
            va = *(const float4*)(Xrow  + kn);
            vb = *(const float4*)(Wirow + kn);
        }
#pragma unroll
        for (int kk = 0; kk < GKT; kk++) {
            ulonglong2 a01 = *(const ulonglong2*)&As[cur][kk][r0];
            ulonglong2 a23 = *(const ulonglong2*)&As[cur][kk][r0 + 4];
            float4 b03 = *(const float4*)&Bs[cur][kk][tx * 8];
            float4 b47 = *(const float4*)&Bs[cur][kk][tx * 8 + 4];
            unsigned long long b2[8];
            b2[0] = pack2(b03.x); b2[1] = pack2(b03.y);
            b2[2] = pack2(b03.z); b2[3] = pack2(b03.w);
            b2[4] = pack2(b47.x); b2[5] = pack2(b47.y);
            b2[6] = pack2(b47.z); b2[7] = pack2(b47.w);
#pragma unroll
            for (int j = 0; j < 8; j++) {
                fma2(acc[0][j], a01.x, b2[j]);
                fma2(acc[1][j], a01.y, b2[j]);
                fma2(acc[2][j], a23.x, b2[j]);
                fma2(acc[3][j], a23.y, b2[j]);
            }
        }
        if (pre) {
            As[nxt][lkq + 0][lrow] = va.x; As[nxt][lkq + 1][lrow] = va.y;
            As[nxt][lkq + 2][lrow] = va.z; As[nxt][lkq + 3][lrow] = va.w;
            Bs[nxt][lkq + 0][lrow] = vb.x; Bs[nxt][lkq + 1][lrow] = vb.y;
            Bs[nxt][lkq + 2][lrow] = vb.z; Bs[nxt][lkq + 3][lrow] = vb.w;
        }
        __syncthreads();
    }

    float bias[8];
#pragma unroll
    for (int j = 0; j < 8; j++) {
        int n = nbase + tx * 8 + j;
        bias[j] = bi[n] + bh[n];
    }
#pragma unroll
    for (int p = 0; p < 4; p++) {
        float lo[8], hi[8];
#pragma unroll
        for (int j = 0; j < 8; j++) {
            float2 v = unpack2(acc[p][j]);
            lo[j] = v.x + bias[j];
            hi[j] = v.y + bias[j];
        }
        size_t mA = (size_t)(mbase + r0 + 2 * p);
        float* dA = &g_gin[mA * NG + nbase + tx * 8];
        float* dB = dA + NG;
        *(float4*)(dA)     = make_float4(lo[0], lo[1], lo[2], lo[3]);
        *(float4*)(dA + 4) = make_float4(lo[4], lo[5], lo[6], lo[7]);
        *(float4*)(dB)     = make_float4(hi[0], hi[1], hi[2], hi[3]);
        *(float4*)(dB + 4) = make_float4(hi[4], hi[5], hi[6], hi[7]);
    }

    // publish: this m-tile's n-stripe is done
    __threadfence();
    __syncthreads();
    if (tid == 0) atomicAdd(&g_mt_cnt[blockIdx.y], 1u);
}

// ---------------------------------------------------------------------------
// Grid-wide barrier  [PROVEN]
// ---------------------------------------------------------------------------
__device__ __forceinline__ void grid_barrier() {
    __threadfence();
    __syncthreads();
    if (threadIdx.x == 0) {
        unsigned gen = atomicAdd(&g_bar_gen, 0u);
        unsigned t   = atomicAdd(&g_bar_count, 1u);
        if (t == gridDim.x - 1) {
            atomicExch(&g_bar_count, 0u);
            atomicAdd(&g_bar_gen, 1u);
        } else {
            while (atomicAdd(&g_bar_gen, 0u) == gen) __nanosleep(64);
        }
    }
    __syncthreads();
}

__device__ __forceinline__ float sigmoidf_(float x) {
    return 1.0f / (1.0f + expf(-x));
}

// ---------------------------------------------------------------------------
// Kernel 2: persistent recurrence [proven R7 core]. Runs CONCURRENTLY with
// gemm_input: at each step waits for g_mt_cnt[t>>1]==32, then reads t-major
// gin rows t*64+b (contiguous). 128-reg cap for co-residency with the gemm.
// ---------------------------------------------------------------------------
#define RKT 32
extern __shared__ float Wsp[];   // 1024 x 32 floats = 128 KB

__global__ __launch_bounds__(256, 2) void lstm_recurrent(const float* __restrict__ Wh,
                                                         const float* __restrict__ h0in,
                                                         const float* __restrict__ c0in,
                                                         float* __restrict__ hidden,
                                                         float* __restrict__ hfin,
                                                         float* __restrict__ cfin) {
    __shared__ float Hs[2][RKT][68];
    __shared__ float Pre[64][36];
    unsigned long long (*Red)[8] = (unsigned long long(*)[8])&Hs[0][0][0];

    const int tid = threadIdx.x;
    const int c   = blockIdx.x;
    const int u0  = c * 8;

    const int kp = tid >> 7;
    const int tl = tid & 127;
    const int r0 = (tl >> 3) * 4;
    const int n0 = (tl & 7) * 4;

    const int wn  = tid >> 3;
    const int wkq = (tid & 7) * 4;
    const int wgcol = (wn >> 3) * HID + u0 + (wn & 7);
    const float* Wrow = Wh + (size_t)wgcol * HID;

    const int hm0 = tid >> 3;
    const int hm1 = hm0 + 32;
    const int hkq = (tid & 7) * 4;

    const int gcol = (n0 >> 3) * HID + u0 + (n0 & 7);

    const int NCHUNK = HID / RKT;

    // ---- load this CTA's Wh slice into persistent smem (once) ----
#pragma unroll 4
    for (int kb = 0; kb < 32; kb++) {
        int k = kb * 32 + wkq;
        float4 wv = *(const float4*)(Wrow + k);
        Wsp[(k + 0) * 32 + wn] = wv.x;
        Wsp[(k + 1) * 32 + wn] = wv.y;
        Wsp[(k + 2) * 32 + wn] = wv.z;
        Wsp[(k + 3) * 32 + wn] = wv.w;
    }
    __syncthreads();

    for (int t = 0; t < SEQ; t++) {
        const float* hsrc = (t == 0) ? h0in : g_hbuf[t & 1];
        float*       hdst = g_hbuf[(t + 1) & 1];

        // ---- wait until the gemm has produced gin for this step ----
        if (tid == 0) {
            while (((volatile unsigned*)g_mt_cnt)[t >> 1] < 32u) __nanosleep(64);
        }
        __syncthreads();

        // gin prefetch (t-major rows t*64+b; L2-coherent)
        float4 g0, g1, g2, g3;
        if (kp == 0) {
            size_t gb = ((size_t)(t * 64 + r0)) * NG + gcol;
            g0 = __ldcg((const float4*)&g_gin[gb]);
            g1 = __ldcg((const float4*)&g_gin[gb + NG]);
            g2 = __ldcg((const float4*)&g_gin[gb + 2 * NG]);
            g3 = __ldcg((const float4*)&g_gin[gb + 3 * NG]);
        }

        {   // prologue: load h chunk 0
            float4 h0v = __ldcg((const float4*)(hsrc + hm0 * HID + hkq));
            float4 h1v = __ldcg((const float4*)(hsrc + hm1 * HID + hkq));
            Hs[0][hkq + 0][hm0] = h0v.x; Hs[0][hkq + 1][hm0] = h0v.y;
            Hs[0][hkq + 2][hm0] = h0v.z; Hs[0][hkq + 3][hm0] = h0v.w;
            Hs[0][hkq + 0][hm1] = h1v.x; Hs[0][hkq + 1][hm1] = h1v.y;
            Hs[0][hkq + 2][hm1] = h1v.z; Hs[0][hkq + 3][hm1] = h1v.w;
        }
        __syncthreads();

        unsigned long long acc[2][4];
#pragma unroll
        for (int p = 0; p < 2; p++)
#pragma unroll
            for (int j = 0; j < 4; j++) acc[p][j] = 0ull;

        for (int ck = 0; ck < NCHUNK; ck++) {
            const int cur = ck & 1;
            const int nxt = cur ^ 1;
            const bool pre = (ck + 1) < NCHUNK;
            float4 ph0, ph1;
            if (pre) {
                int kn = (ck + 1) * RKT;
                ph0 = __ldcg((const float4*)(hsrc + hm0 * HID + kn + hkq));
                ph1 = __ldcg((const float4*)(hsrc + hm1 * HID + kn + hkq));
            }
            const float* Wc = Wsp + ck * RKT * 32;
#pragma unroll
            for (int i = 0; i < RKT / 2; i++) {
                const int kk = 2 * i + kp;
                ulonglong2 a = *(const ulonglong2*)&Hs[cur][kk][r0];
                float4 bv = *(const float4*)&Wc[kk * 32 + n0];
                unsigned long long b0 = pack2(bv.x);
                unsigned long long b1 = pack2(bv.y);
                unsigned long long b2 = pack2(bv.z);
                unsigned long long b3 = pack2(bv.w);
                fma2(acc[0][0], a.x, b0); fma2(acc[0][1], a.x, b1);
                fma2(acc[0][2], a.x, b2); fma2(acc[0][3], a.x, b3);
                fma2(acc[1][0], a.y, b0); fma2(acc[1][1], a.y, b1);
                fma2(acc[1][2], a.y, b2); fma2(acc[1][3], a.y, b3);
            }
            if (pre) {
                Hs[nxt][hkq + 0][hm0] = ph0.x; Hs[nxt][hkq + 1][hm0] = ph0.y;
                Hs[nxt][hkq + 2][hm0] = ph0.z; Hs[nxt][hkq + 3][hm0] = ph0.w;
                Hs[nxt][hkq + 0][hm1] = ph1.x; Hs[nxt][hkq + 1][hm1] = ph1.y;
                Hs[nxt][hkq + 2][hm1] = ph1.z; Hs[nxt][hkq + 3][hm1] = ph1.w;
            }
            __syncthreads();
        }

        // ---- combine the two K-parity halves ----
        if (kp == 1) {
#pragma unroll
            for (int p = 0; p < 2; p++)
#pragma unroll
                for (int j = 0; j < 4; j++)
                    Red[tl][(p * 4 + j + tl) & 7] = acc[p][j];
        }
        __syncthreads();
        if (kp == 0) {
#pragma unroll
            for (int p = 0; p < 2; p++)
#pragma unroll
                for (int j = 0; j < 4; j++)
                    add2(acc[p][j], Red[tl][(p * 4 + j + tl) & 7]);

            float2 u0v = unpack2(acc[0][0]), u1v = unpack2(acc[0][1]);
            float2 u2v = unpack2(acc[0][2]), u3v = unpack2(acc[0][3]);
            float2 v0v = unpack2(acc[1][0]), v1v = unpack2(acc[1][1]);
            float2 v2v = unpack2(acc[1][2]), v3v = unpack2(acc[1][3]);
            *(float4*)&Pre[r0 + 0][n0] =
                make_float4(u0v.x + g0.x, u1v.x + g0.y, u2v.x + g0.z, u3v.x + g0.w);
            *(float4*)&Pre[r0 + 1][n0] =
                make_float4(u0v.y + g1.x, u1v.y + g1.y, u2v.y + g1.z, u3v.y + g1.w);
            *(float4*)&Pre[r0 + 2][n0] =
                make_float4(v0v.x + g2.x, v1v.x + g2.y, v2v.x + g2.z, v3v.x + g2.w);
            *(float4*)&Pre[r0 + 3][n0] =
                make_float4(v0v.y + g3.x, v1v.y + g3.y, v2v.y + g3.z, v3v.y + g3.w);
        }
        __syncthreads();

        // ---- gate math ----
#pragma unroll
        for (int p = 0; p < 2; p++) {
            int e  = tid + p * 256;
            int b  = e >> 3;
            int ui = e & 7;
            int u  = u0 + ui;
            int ce = b * HID + u;
            float ig = sigmoidf_(Pre[b][ui]);
            float fg = sigmoidf_(Pre[b][8 + ui]);
            float gg = tanhf(Pre[b][16 + ui]);
            float og = sigmoidf_(Pre[b][24 + ui]);
            float cprev = (t == 0) ? c0in[ce] : g_c[ce];
            float cnew = fg * cprev + ig * gg;
            float hnew = og * tanhf(cnew);
            g_c[ce]  = cnew;
            hdst[ce] = hnew;
            hidden[((size_t)b * SEQ + t) * HID + u] = hnew;
            if (t == SEQ - 1) { hfin[ce] = hnew; cfin[ce] = cnew; }
        }

        grid_barrier();
    }
}

// ---------------------------------------------------------------------------
// kernel_launch: fork-join graph — {transpose -> gemm} on s1  ||  lstm on s0
// ---------------------------------------------------------------------------
extern "C" void kernel_launch(void* const* d_in, const int* in_sizes, int n_in,
                              void* d_out, int out_size) {
    const float* X   = (const float*)d_in[0];
    const float* h0  = (const float*)d_in[1];
    const float* c0  = (const float*)d_in[2];
    const float* Wi  = (const float*)d_in[3];
    const float* Wh  = (const float*)d_in[4];
    const float* bi  = (const float*)d_in[5];
    const float* bh  = (const float*)d_in[6];

    float* out    = (float*)d_out;
    float* hidden = out;
    float* hfin   = out + (size_t)BATCH * SEQ * HID;
    float* cfin   = hfin + (size_t)BATCH * HID;

    const int WSMEM = HID * 32 * (int)sizeof(float);   // 128 KB dynamic

    static cudaStream_t s1;
    static cudaEvent_t evF, evJ;
    static int inited = 0;
    if (!inited) {
        cudaStreamCreateWithFlags(&s1, cudaStreamNonBlocking);
        cudaEventCreateWithFlags(&evF, cudaEventDisableTiming);
        cudaEventCreateWithFlags(&evJ, cudaEventDisableTiming);
        cudaFuncSetAttribute(lstm_recurrent,
                             cudaFuncAttributeMaxDynamicSharedMemorySize, WSMEM);
        inited = 1;
    }

    reset_cnt<<<1, 128>>>();

    cudaEventRecord(evF, 0);
    cudaStreamWaitEvent(s1, evF, 0);

    transpose_x<<<(MTOT * INP / 4) / 256, 256, 0, s1>>>(X);
    gemm_input<<<dim3(NG / 128, MTOT / 128), 256, 0, s1>>>(Wi, bi, bh);

    lstm_recurrent<<<NCTA, 256, WSMEM>>>(Wh, h0, c0, hidden, hfin, cfin);

    cudaEventRecord(evJ, s1);
    cudaStreamWaitEvent(0, evJ, 0);
}

// round 10
// speedup vs baseline: 2.2326x; 2.2326x over previous
#include <cuda_runtime.h>
#include <cuda_bf16.h>

#define BATCH 64
#define SEQ   256
#define INP   1024
#define HID   1024
#define NG    4096
#define MTOT  (BATCH*SEQ)
#define NCTA  128

// -------- device scratch ----------
__device__ float g_gin[(size_t)MTOT * NG];   // 256 MB: X @ Wi^T + b_i + b_h
__device__ float g_hbuf[2][BATCH * HID];     // double-buffered hidden state
__device__ float g_c[BATCH * HID];
__device__ unsigned g_bar_count = 0;
__device__ unsigned g_bar_gen   = 0;

// -------- packed f32x2 helpers ----------
__device__ __forceinline__ unsigned long long pack2(float x) {
    unsigned long long r;
    unsigned xi = __float_as_uint(x);
    asm("mov.b64 %0, {%1, %1};" : "=l"(r) : "r"(xi));
    return r;
}
__device__ __forceinline__ void fma2(unsigned long long& d,
                                     unsigned long long a,
                                     unsigned long long b) {
    asm("fma.rn.f32x2 %0, %1, %2, %0;" : "+l"(d) : "l"(a), "l"(b));
}
__device__ __forceinline__ void add2(unsigned long long& d, unsigned long long s) {
    asm("add.rn.f32x2 %0, %0, %1;" : "+l"(d) : "l"(s));
}
__device__ __forceinline__ float2 unpack2(unsigned long long v) {
    unsigned lo, hi;
    asm("mov.b64 {%0, %1}, %2;" : "=r"(lo), "=r"(hi) : "l"(v));
    float2 f;
    f.x = __uint_as_float(lo);
    f.y = __uint_as_float(hi);
    return f;
}

// ---------------------------------------------------------------------------
// Kernel 1: Gin = X @ Wi^T + (b_i + b_h)
// [PROVEN R7 core; ONLY change: __launch_bounds__(256,2) -> 128-reg cap,
//  2 CTAs/SM for latency hiding]
// ---------------------------------------------------------------------------
#define GKT 8
__global__ __launch_bounds__(256, 2) void gemm_input(const float* __restrict__ X,
                                                     const float* __restrict__ Wi,
                                                     const float* __restrict__ bi,
                                                     const float* __restrict__ bh) {
    __shared__ float As[2][GKT][132];
    __shared__ float Bs[2][GKT][132];

    const int tid   = threadIdx.x;
    const int mbase = blockIdx.y * 128;
    const int nbase = blockIdx.x * 128;
    const int ty    = tid >> 4;
    const int tx    = tid & 15;
    const int r0    = ty * 8;
    const int lrow  = tid >> 1;
    const int lkq   = (tid & 1) * 4;

    const float* Xrow  = X  + (size_t)(mbase + lrow) * INP + lkq;
    const float* Wirow = Wi + (size_t)(nbase + lrow) * INP + lkq;

    unsigned long long acc[4][8];
#pragma unroll
    for (int i = 0; i < 4; i++)
#pragma unroll
        for (int j = 0; j < 8; j++) acc[i][j] = 0ull;

    {
        float4 va = *(const float4*)(Xrow);
        float4 vb = *(const float4*)(Wirow);
        As[0][lkq + 0][lrow] = va.x; As[0][lkq + 1][lrow] = va.y;
        As[0][lkq + 2][lrow] = va.z; As[0][lkq + 3][lrow] = va.w;
        Bs[0][lkq + 0][lrow] = vb.x; Bs[0][lkq + 1][lrow] = vb.y;
        Bs[0][lkq + 2][lrow] = vb.z; Bs[0][lkq + 3][lrow] = vb.w;
    }
    __syncthreads();

    const int NCHUNK = INP / GKT;
    for (int ck = 0; ck < NCHUNK; ck++) {
        const int cur = ck & 1;
        const int nxt = cur ^ 1;
        const bool pre = (ck + 1) < NCHUNK;
        float4 va, vb;
        if (pre) {
            int kn = (ck + 1) * GKT;
            va = *(const float4*)(Xrow  + kn);
            vb = *(const float4*)(Wirow + kn);
        }
#pragma unroll
        for (int kk = 0; kk < GKT; kk++) {
            ulonglong2 a01 = *(const ulonglong2*)&As[cur][kk][r0];
            ulonglong2 a23 = *(const ulonglong2*)&As[cur][kk][r0 + 4];
            float4 b03 = *(const float4*)&Bs[cur][kk][tx * 8];
            float4 b47 = *(const float4*)&Bs[cur][kk][tx * 8 + 4];
            unsigned long long b2[8];
            b2[0] = pack2(b03.x); b2[1] = pack2(b03.y);
            b2[2] = pack2(b03.z); b2[3] = pack2(b03.w);
            b2[4] = pack2(b47.x); b2[5] = pack2(b47.y);
            b2[6] = pack2(b47.z); b2[7] = pack2(b47.w);
#pragma unroll
            for (int j = 0; j < 8; j++) {
                fma2(acc[0][j], a01.x, b2[j]);
                fma2(acc[1][j], a01.y, b2[j]);
                fma2(acc[2][j], a23.x, b2[j]);
                fma2(acc[3][j], a23.y, b2[j]);
            }
        }
        if (pre) {
            As[nxt][lkq + 0][lrow] = va.x; As[nxt][lkq + 1][lrow] = va.y;
            As[nxt][lkq + 2][lrow] = va.z; As[nxt][lkq + 3][lrow] = va.w;
            Bs[nxt][lkq + 0][lrow] = vb.x; Bs[nxt][lkq + 1][lrow] = vb.y;
            Bs[nxt][lkq + 2][lrow] = vb.z; Bs[nxt][lkq + 3][lrow] = vb.w;
        }
        __syncthreads();
    }

    float bias[8];
#pragma unroll
    for (int j = 0; j < 8; j++) {
        int n = nbase + tx * 8 + j;
        bias[j] = bi[n] + bh[n];
    }
#pragma unroll
    for (int p = 0; p < 4; p++) {
        float lo[8], hi[8];
#pragma unroll
        for (int j = 0; j < 8; j++) {
            float2 v = unpack2(acc[p][j]);
            lo[j] = v.x + bias[j];
            hi[j] = v.y + bias[j];
        }
        size_t mA = (size_t)(mbase + r0 + 2 * p);
        float* dA = &g_gin[mA * NG + nbase + tx * 8];
        float* dB = dA + NG;
        *(float4*)(dA)     = make_float4(lo[0], lo[1], lo[2], lo[3]);
        *(float4*)(dA + 4) = make_float4(lo[4], lo[5], lo[6], lo[7]);
        *(float4*)(dB)     = make_float4(hi[0], hi[1], hi[2], hi[3]);
        *(float4*)(dB + 4) = make_float4(hi[4], hi[5], hi[6], hi[7]);
    }
}

// ---------------------------------------------------------------------------
// Grid-wide barrier [PROVEN arrival; waiter poll switched RMW -> volatile load]
// ---------------------------------------------------------------------------
__device__ __forceinline__ void grid_barrier() {
    __threadfence();
    __syncthreads();
    if (threadIdx.x == 0) {
        unsigned gen = *(volatile unsigned*)&g_bar_gen;
        unsigned t   = atomicAdd(&g_bar_count, 1u);
        if (t == gridDim.x - 1) {
            atomicExch(&g_bar_count, 0u);
            atomicAdd(&g_bar_gen, 1u);
        } else {
            while (*(volatile unsigned*)&g_bar_gen == gen) __nanosleep(64);
        }
    }
    __syncthreads();
}

__device__ __forceinline__ float sigmoidf_(float x) {
    return 1.0f / (1.0f + expf(-x));
}

// ---------------------------------------------------------------------------
// Kernel 2: persistent recurrence [PROVEN R7 — unchanged]
// ---------------------------------------------------------------------------
#define RKT 32
extern __shared__ float Wsp[];   // 1024 x 32 floats = 128 KB

__global__ __launch_bounds__(256, 1) void lstm_recurrent(const float* __restrict__ Wh,
                                                         const float* __restrict__ h0in,
                                                         const float* __restrict__ c0in,
                                                         float* __restrict__ hidden,
                                                         float* __restrict__ hfin,
                                                         float* __restrict__ cfin) {
    __shared__ float Hs[2][RKT][68];    // [buf][k][m 0..63]  (17408 B)
    __shared__ float Pre[64][36];       // pre-activations    (9216 B)
    unsigned long long (*Red)[8] = (unsigned long long(*)[8])&Hs[0][0][0];

    const int tid = threadIdx.x;
    const int c   = blockIdx.x;
    const int u0  = c * 8;

    const int kp = tid >> 7;            // K parity (0/1)
    const int tl = tid & 127;
    const int r0 = (tl >> 3) * 4;       // rows r0..r0+3 (batch)
    const int n0 = (tl & 7) * 4;        // local cols n0..n0+3

    const int wn  = tid >> 3;
    const int wkq = (tid & 7) * 4;
    const int wgcol = (wn >> 3) * HID + u0 + (wn & 7);
    const float* Wrow = Wh + (size_t)wgcol * HID;

    const int hm0 = tid >> 3;           // 0..31
    const int hm1 = hm0 + 32;
    const int hkq = (tid & 7) * 4;

    const int gcol = (n0 >> 3) * HID + u0 + (n0 & 7);

    const int NCHUNK = HID / RKT;       // 32

    // ---- load this CTA's Wh slice into persistent smem (once) ----
#pragma unroll 4
    for (int kb = 0; kb < 32; kb++) {
        int k = kb * 32 + wkq;
        float4 wv = *(const float4*)(Wrow + k);
        Wsp[(k + 0) * 32 + wn] = wv.x;
        Wsp[(k + 1) * 32 + wn] = wv.y;
        Wsp[(k + 2) * 32 + wn] = wv.z;
        Wsp[(k + 3) * 32 + wn] = wv.w;
    }
    __syncthreads();

    for (int t = 0; t < SEQ; t++) {
        const float* hsrc = (t == 0) ? h0in : g_hbuf[t & 1];
        float*       hdst = g_hbuf[(t + 1) & 1];

        // gin prefetch (independent of h)
        float4 g0, g1, g2, g3;
        if (kp == 0) {
            size_t gb = ((size_t)r0 * SEQ + t) * NG + gcol;
            g0 = *(const float4*)&g_gin[gb];
            g1 = *(const float4*)&g_gin[gb + (size_t)SEQ * NG];
            g2 = *(const float4*)&g_gin[gb + 2 * (size_t)SEQ * NG];
            g3 = *(const float4*)&g_gin[gb + 3 * (size_t)SEQ * NG];
        }

        {   // prologue: load h chunk 0
            float4 h0v = __ldcg((const float4*)(hsrc + hm0 * HID + hkq));
            float4 h1v = __ldcg((const float4*)(hsrc + hm1 * HID + hkq));
            Hs[0][hkq + 0][hm0] = h0v.x; Hs[0][hkq + 1][hm0] = h0v.y;
            Hs[0][hkq + 2][hm0] = h0v.z; Hs[0][hkq + 3][hm0] = h0v.w;
            Hs[0][hkq + 0][hm1] = h1v.x; Hs[0][hkq + 1][hm1] = h1v.y;
            Hs[0][hkq + 2][hm1] = h1v.z; Hs[0][hkq + 3][hm1] = h1v.w;
        }
        __syncthreads();

        unsigned long long acc[2][4];
#pragma unroll
        for (int p = 0; p < 2; p++)
#pragma unroll
            for (int j = 0; j < 4; j++) acc[p][j] = 0ull;

        for (int ck = 0; ck < NCHUNK; ck++) {
            const int cur = ck & 1;
            const int nxt = cur ^ 1;
            const bool pre = (ck + 1) < NCHUNK;
            float4 ph0, ph1;
            if (pre) {
                int kn = (ck + 1) * RKT;
                ph0 = __ldcg((const float4*)(hsrc + hm0 * HID + kn + hkq));
                ph1 = __ldcg((const float4*)(hsrc + hm1 * HID + kn + hkq));
            }
            const float* Wc = Wsp + ck * RKT * 32;
#pragma unroll
            for (int i = 0; i < RKT / 2; i++) {
                const int kk = 2 * i + kp;
                ulonglong2 a = *(const ulonglong2*)&Hs[cur][kk][r0];
                float4 bv = *(const float4*)&Wc[kk * 32 + n0];
                unsigned long long b0 = pack2(bv.x);
                unsigned long long b1 = pack2(bv.y);
                unsigned long long b2 = pack2(bv.z);
                unsigned long long b3 = pack2(bv.w);
                fma2(acc[0][0], a.x, b0); fma2(acc[0][1], a.x, b1);
                fma2(acc[0][2], a.x, b2); fma2(acc[0][3], a.x, b3);
                fma2(acc[1][0], a.y, b0); fma2(acc[1][1], a.y, b1);
                fma2(acc[1][2], a.y, b2); fma2(acc[1][3], a.y, b3);
            }
            if (pre) {
                Hs[nxt][hkq + 0][hm0] = ph0.x; Hs[nxt][hkq + 1][hm0] = ph0.y;
                Hs[nxt][hkq + 2][hm0] = ph0.z; Hs[nxt][hkq + 3][hm0] = ph0.w;
                Hs[nxt][hkq + 0][hm1] = ph1.x; Hs[nxt][hkq + 1][hm1] = ph1.y;
                Hs[nxt][hkq + 2][hm1] = ph1.z; Hs[nxt][hkq + 3][hm1] = ph1.w;
            }
            __syncthreads();
        }

        // ---- combine the two K-parity halves (Red aliases Hs[0]) ----
        if (kp == 1) {
#pragma unroll
            for (int p = 0; p < 2; p++)
#pragma unroll
                for (int j = 0; j < 4; j++)
                    Red[tl][(p * 4 + j + tl) & 7] = acc[p][j];
        }
        __syncthreads();
        if (kp == 0) {
#pragma unroll
            for (int p = 0; p < 2; p++)
#pragma unroll
                for (int j = 0; j < 4; j++)
                    add2(acc[p][j], Red[tl][(p * 4 + j + tl) & 7]);

            float2 u0v = unpack2(acc[0][0]), u1v = unpack2(acc[0][1]);
            float2 u2v = unpack2(acc[0][2]), u3v = unpack2(acc[0][3]);
            float2 v0v = unpack2(acc[1][0]), v1v = unpack2(acc[1][1]);
            float2 v2v = unpack2(acc[1][2]), v3v = unpack2(acc[1][3]);
            *(float4*)&Pre[r0 + 0][n0] =
                make_float4(u0v.x + g0.x, u1v.x + g0.y, u2v.x + g0.z, u3v.x + g0.w);
            *(float4*)&Pre[r0 + 1][n0] =
                make_float4(u0v.y + g1.x, u1v.y + g1.y, u2v.y + g1.z, u3v.y + g1.w);
            *(float4*)&Pre[r0 + 2][n0] =
                make_float4(v0v.x + g2.x, v1v.x + g2.y, v2v.x + g2.z, v3v.x + g2.w);
            *(float4*)&Pre[r0 + 3][n0] =
                make_float4(v0v.y + g3.x, v1v.y + g3.y, v2v.y + g3.z, v3v.y + g3.w);
        }
        __syncthreads();

        // ---- gate math: 512 elements, 2 per thread ----
#pragma unroll
        for (int p = 0; p < 2; p++) {
            int e  = tid + p * 256;
            int b  = e >> 3;
            int ui = e & 7;
            int u  = u0 + ui;
            int ce = b * HID + u;
            float ig = sigmoidf_(Pre[b][ui]);
            float fg = sigmoidf_(Pre[b][8 + ui]);
            float gg = tanhf(Pre[b][16 + ui]);
            float og = sigmoidf_(Pre[b][24 + ui]);
            float cprev = (t == 0) ? c0in[ce] : g_c[ce];
            float cnew = fg * cprev + ig * gg;
            float hnew = og * tanhf(cnew);
            g_c[ce]  = cnew;
            hdst[ce] = hnew;
            hidden[((size_t)b * SEQ + t) * HID + u] = hnew;
            if (t == SEQ - 1) { hfin[ce] = hnew; cfin[ce] = cnew; }
        }

        grid_barrier();
    }
}

// ---------------------------------------------------------------------------
// kernel_launch
// ---------------------------------------------------------------------------
extern "C" void kernel_launch(void* const* d_in, const int* in_sizes, int n_in,
                              void* d_out, int out_size) {
    const float* X   = (const float*)d_in[0];
    const float* h0  = (const float*)d_in[1];
    const float* c0  = (const float*)d_in[2];
    const float* Wi  = (const float*)d_in[3];
    const float* Wh  = (const float*)d_in[4];
    const float* bi  = (const float*)d_in[5];
    const float* bh  = (const float*)d_in[6];

    float* out    = (float*)d_out;
    float* hidden = out;
    float* hfin   = out + (size_t)BATCH * SEQ * HID;
    float* cfin   = hfin + (size_t)BATCH * HID;

    const int WSMEM = HID * 32 * (int)sizeof(float);   // 128 KB dynamic
    static int attr_done = 0;
    if (!attr_done) {
        cudaFuncSetAttribute(lstm_recurrent,
                             cudaFuncAttributeMaxDynamicSharedMemorySize, WSMEM);
        attr_done = 1;
    }

    gemm_input<<<dim3(NG / 128, MTOT / 128), 256>>>(X, Wi, bi, bh);
    lstm_recurrent<<<NCTA, 256, WSMEM>>>(Wh, h0, c0, hidden, hfin, cfin);
}